// round 1
// baseline (speedup 1.0000x reference)
#include <cuda_runtime.h>
#include <math.h>

#define NMAX    100000
#define EMAX    1600000
#define NTYPES  17
#define DIM     128
#define GMAX    64
#define NBMAX   128     // max scan blocks (ceil(NMAX/1024)=98)

// ---------------- static scratch (no runtime allocation allowed) ----------------
__device__ int   g_cnt[NMAX];
__device__ int   g_cur[NMAX];
__device__ int   g_rowptr[NMAX + 1];
__device__ int   g_bsums[NBMAX];
__device__ int   g_srcA[EMAX];
__device__ float g_wA[EMAX];     // dinv[src] per CSR edge
__device__ int   g_typA[EMAX];   // node_ids[src] per CSR edge
__device__ float g_dinv[NMAX];
__device__ float g_htab[NTYPES * DIM];     // emb_table @ W1
__device__ float g_y1[(size_t)NMAX * DIM]; // relu(conv1)
__device__ float g_y2[(size_t)NMAX * DIM]; // Agg(y1)
__device__ float g_pool[GMAX * DIM];
__device__ int   g_gcnt[GMAX];

// ---------------- kernels ----------------

__global__ void k_zero_cnt(int n) {
    int i = blockIdx.x * blockDim.x + threadIdx.x;
    if (i < n) g_cnt[i] = 0;
}

__global__ void k_hist(const int* __restrict__ ei, int E) {
    int e = blockIdx.x * blockDim.x + threadIdx.x;
    if (e < E) atomicAdd(&g_cnt[ei[E + e]], 1);
}

// per-block inclusive scan; writes local-exclusive to rowptr, total to bsums.
// Also computes dinv = rsqrt(in_degree + 1) (self-loop included).
__global__ void k_scan1(int n) {
    __shared__ int s[1024];
    int t = threadIdx.x;
    int i = blockIdx.x * 1024 + t;
    int v = (i < n) ? g_cnt[i] : 0;
    if (i < n) g_dinv[i] = rsqrtf((float)(v + 1));
    s[t] = v;
    __syncthreads();
    #pragma unroll
    for (int off = 1; off < 1024; off <<= 1) {
        int a = (t >= off) ? s[t - off] : 0;
        __syncthreads();
        s[t] += a;
        __syncthreads();
    }
    if (i < n) g_rowptr[i] = s[t] - v;          // local exclusive
    if (t == 1023) g_bsums[blockIdx.x] = s[1023];
}

__global__ void k_scan2(int nb) {
    __shared__ int s[NBMAX];
    int t = threadIdx.x;
    int v = (t < nb) ? g_bsums[t] : 0;
    s[t] = v;
    __syncthreads();
    #pragma unroll
    for (int off = 1; off < NBMAX; off <<= 1) {
        int a = (t >= off) ? s[t - off] : 0;
        __syncthreads();
        s[t] += a;
        __syncthreads();
    }
    if (t < nb) g_bsums[t] = s[t] - v;          // exclusive block offsets
}

__global__ void k_scan3(int n, int E) {
    int i = blockIdx.x * blockDim.x + threadIdx.x;
    if (i < n) {
        g_rowptr[i] += g_bsums[i >> 10];
        g_cur[i] = 0;
    }
    if (i == 0) g_rowptr[n] = E;
}

// CSR placement; also pack per-edge dinv[src] and node_ids[src]
__global__ void k_scatter(const int* __restrict__ ei, const int* __restrict__ node_ids, int E) {
    int e = blockIdx.x * blockDim.x + threadIdx.x;
    if (e >= E) return;
    int s = ei[e];
    int d = ei[E + e];
    int p = atomicAdd(&g_cur[d], 1);
    int idx = g_rowptr[d] + p;
    g_srcA[idx] = s;
    g_wA[idx]   = g_dinv[s];
    g_typA[idx] = node_ids[s];
}

// h_table = emb_table @ W1   (17x128 @ 128x128)
__global__ void k_htab(const float* __restrict__ emb, const float* __restrict__ W1) {
    int idx = blockIdx.x * blockDim.x + threadIdx.x;
    if (idx >= NTYPES * DIM) return;
    int t = idx / DIM, o = idx % DIM;
    float acc = 0.f;
    #pragma unroll 8
    for (int d = 0; d < DIM; d++) acc = fmaf(emb[t * DIM + d], W1[d * DIM + o], acc);
    g_htab[idx] = acc;
}

// Layer 1: y1[i] = relu( sum_{e: dst=i} dinv[src]*dinv[i]*h_table[typ(src)] + dinv[i]^2*h_table[typ(i)] + b1 )
__global__ void __launch_bounds__(256) k_layer1(const int* __restrict__ node_ids,
                                                const float* __restrict__ b1, int n) {
    __shared__ float4 sh[NTYPES * 32];   // h_table as float4 rows (17 x 32)
    __shared__ float4 sb[32];            // b1
    for (int i = threadIdx.x; i < NTYPES * 32; i += blockDim.x)
        sh[i] = ((const float4*)g_htab)[i];
    if (threadIdx.x < 32) sb[threadIdx.x] = ((const float4*)b1)[threadIdx.x];
    __syncthreads();

    int warp = threadIdx.x >> 5, lane = threadIdx.x & 31;
    int i = blockIdx.x * 8 + warp;
    if (i >= n) return;

    float di = g_dinv[i];
    int e0 = g_rowptr[i], e1 = g_rowptr[i + 1];
    float ws = di * di;                                    // self-loop norm
    float4 h = sh[node_ids[i] * 32 + lane];
    float4 acc;
    acc.x = ws * h.x; acc.y = ws * h.y; acc.z = ws * h.z; acc.w = ws * h.w;

    for (int e = e0; e < e1; e++) {
        float we = g_wA[e] * di;
        float4 v = sh[g_typA[e] * 32 + lane];
        acc.x = fmaf(we, v.x, acc.x);
        acc.y = fmaf(we, v.y, acc.y);
        acc.z = fmaf(we, v.z, acc.z);
        acc.w = fmaf(we, v.w, acc.w);
    }
    float4 bb = sb[lane];
    acc.x = fmaxf(acc.x + bb.x, 0.f);
    acc.y = fmaxf(acc.y + bb.y, 0.f);
    acc.z = fmaxf(acc.z + bb.z, 0.f);
    acc.w = fmaxf(acc.w + bb.w, 0.f);
    ((float4*)g_y1)[i * 32 + lane] = acc;
}

// Layer 2 aggregation only (W2/b2 deferred past pooling): y2 = Agg(y1)
__global__ void __launch_bounds__(256) k_layer2(int n) {
    int warp = threadIdx.x >> 5, lane = threadIdx.x & 31;
    int i = blockIdx.x * 8 + warp;
    if (i >= n) return;

    const float4* y14 = (const float4*)g_y1;
    float di = g_dinv[i];
    float ws = di * di;
    float4 a = y14[i * 32 + lane];
    float4 acc;
    acc.x = ws * a.x; acc.y = ws * a.y; acc.z = ws * a.z; acc.w = ws * a.w;

    int e = g_rowptr[i], e1 = g_rowptr[i + 1];
    for (; e + 2 <= e1; e += 2) {
        int s0 = g_srcA[e], s1 = g_srcA[e + 1];
        float w0 = g_wA[e] * di, w1 = g_wA[e + 1] * di;
        float4 v0 = __ldg(&y14[s0 * 32 + lane]);
        float4 v1 = __ldg(&y14[s1 * 32 + lane]);
        acc.x = fmaf(w0, v0.x, acc.x); acc.y = fmaf(w0, v0.y, acc.y);
        acc.z = fmaf(w0, v0.z, acc.z); acc.w = fmaf(w0, v0.w, acc.w);
        acc.x = fmaf(w1, v1.x, acc.x); acc.y = fmaf(w1, v1.y, acc.y);
        acc.z = fmaf(w1, v1.z, acc.z); acc.w = fmaf(w1, v1.w, acc.w);
    }
    if (e < e1) {
        int s0 = g_srcA[e];
        float w0 = g_wA[e] * di;
        float4 v0 = __ldg(&y14[s0 * 32 + lane]);
        acc.x = fmaf(w0, v0.x, acc.x); acc.y = fmaf(w0, v0.y, acc.y);
        acc.z = fmaf(w0, v0.z, acc.z); acc.w = fmaf(w0, v0.w, acc.w);
    }
    ((float4*)g_y2)[i * 32 + lane] = acc;
}

__device__ __forceinline__ int lbound(const int* __restrict__ a, int n, int key) {
    int lo = 0, hi = n;
    while (lo < hi) {
        int m = (lo + hi) >> 1;
        if (a[m] < key) lo = m + 1; else hi = m;
    }
    return lo;
}

// pool: batch is sorted -> contiguous node range per graph; no atomics
__global__ void k_pool(const int* __restrict__ batch, int n) {
    int g = blockIdx.x;
    __shared__ int slo, shi;
    if (threadIdx.x == 0) {
        slo = lbound(batch, n, g);
        shi = lbound(batch, n, g + 1);
    }
    __syncthreads();
    int lo = slo, hi = shi;
    float acc = 0.f;
    for (int r = lo; r < hi; r++)
        acc += g_y2[(size_t)r * DIM + threadIdx.x];
    g_pool[g * DIM + threadIdx.x] = acc;
    if (threadIdx.x == 0) g_gcnt[g] = hi - lo;
}

// out[g] = (pool[g]/cnt[g]) @ W2 + b2   (zero if empty graph)
__global__ void k_final(const float* __restrict__ W2, const float* __restrict__ b2,
                        float* __restrict__ out) {
    int g = blockIdx.x, o = threadIdx.x;
    __shared__ float p[DIM];
    int c = g_gcnt[g];
    float inv = (c > 0) ? (1.0f / (float)c) : 0.f;
    p[o] = g_pool[g * DIM + o] * inv;
    __syncthreads();
    float acc = 0.f;
    #pragma unroll 8
    for (int d = 0; d < DIM; d++) acc = fmaf(p[d], W2[d * DIM + o], acc);
    out[g * DIM + o] = (c > 0) ? (acc + b2[o]) : 0.f;
}

// ---------------- launcher ----------------
extern "C" void kernel_launch(void* const* d_in, const int* in_sizes, int n_in,
                              void* d_out, int out_size) {
    const int* node_ids = (const int*)d_in[0];
    const int* ei       = (const int*)d_in[1];
    const int* batch    = (const int*)d_in[2];
    // num_graphs may or may not be materialized as a size-1 input; detect.
    int base = (n_in >= 9 && in_sizes[3] == 1) ? 4 : 3;
    const float* emb = (const float*)d_in[base + 0];
    const float* W1  = (const float*)d_in[base + 1];
    const float* b1  = (const float*)d_in[base + 2];
    const float* W2  = (const float*)d_in[base + 3];
    const float* b2  = (const float*)d_in[base + 4];

    int N = in_sizes[0];
    int E = in_sizes[1] / 2;
    int G = out_size / DIM;
    int NB = (N + 1023) / 1024;

    k_zero_cnt<<<(N + 255) / 256, 256>>>(N);
    k_hist<<<(E + 255) / 256, 256>>>(ei, E);
    k_scan1<<<NB, 1024>>>(N);
    k_scan2<<<1, NBMAX>>>(NB);
    k_scan3<<<(N + 255) / 256, 256>>>(N, E);
    k_scatter<<<(E + 255) / 256, 256>>>(ei, node_ids, E);
    k_htab<<<(NTYPES * DIM + 255) / 256, 256>>>(emb, W1);
    k_layer1<<<(N + 7) / 8, 256>>>(node_ids, b1, N);
    k_layer2<<<(N + 7) / 8, 256>>>(N);
    k_pool<<<G, DIM>>>(batch, N);
    k_final<<<G, DIM>>>(W2, b2, (float*)d_out);
}

// round 2
// speedup vs baseline: 1.9673x; 1.9673x over previous
#include <cuda_runtime.h>
#include <cuda_fp16.h>
#include <math.h>

#define NMAX    100000
#define EMAX    1600000
#define NTYPES  17
#define DIM     128
#define GMAX    64
#define NBMAX   128

// ---------------- static scratch ----------------
__device__ int    g_cnt[NMAX];
__device__ int    g_cur[NMAX];
__device__ int    g_rowptr[NMAX + 1];
__device__ int    g_bsums[NBMAX];
__device__ int    g_srcA[EMAX];
__device__ float  g_dinv[NMAX];
__device__ float  g_c[(size_t)NMAX * NTYPES];     // per-node type coefficients
__device__ float  g_htab[NTYPES * DIM];           // emb_table @ W1
__device__ __half g_y1h[(size_t)NMAX * DIM];      // dinv[i] * relu(conv1)  (fp16)
__device__ float  g_pool[GMAX * DIM];
__device__ int    g_gcnt[GMAX];

// ---------------- kernels ----------------

// zero everything that must be clean each replay
__global__ void k_init(int n, int g) {
    int i = blockIdx.x * blockDim.x + threadIdx.x;
    if (i < n) { g_cnt[i] = 0; g_cur[i] = 0; }
    if (i < n * NTYPES) g_c[i] = 0.f;
    if (i < g * DIM) g_pool[i] = 0.f;
    if (i < g) g_gcnt[i] = 0;
}

__global__ void k_hist(const int* __restrict__ ei, int E) {
    int e = blockIdx.x * blockDim.x + threadIdx.x;
    if (e < E) atomicAdd(&g_cnt[ei[E + e]], 1);
}

// per-block scan of counts; also dinv = rsqrt(deg+1)
__global__ void k_scan1(int n) {
    __shared__ int s[1024];
    int t = threadIdx.x;
    int i = blockIdx.x * 1024 + t;
    int v = (i < n) ? g_cnt[i] : 0;
    if (i < n) g_dinv[i] = rsqrtf((float)(v + 1));
    s[t] = v;
    __syncthreads();
    #pragma unroll
    for (int off = 1; off < 1024; off <<= 1) {
        int a = (t >= off) ? s[t - off] : 0;
        __syncthreads();
        s[t] += a;
        __syncthreads();
    }
    if (i < n) g_rowptr[i] = s[t] - v;
    if (t == 1023) g_bsums[blockIdx.x] = s[1023];
}

// block 0: scan of block sums;  blocks 1..: h_table = emb @ W1
__global__ void k_misc(int nb, const float* __restrict__ emb, const float* __restrict__ W1) {
    if (blockIdx.x == 0) {
        __shared__ int s[NBMAX];
        int t = threadIdx.x;
        int v = 0;
        if (t < NBMAX) { v = (t < nb) ? g_bsums[t] : 0; s[t] = v; }
        __syncthreads();
        #pragma unroll
        for (int off = 1; off < NBMAX; off <<= 1) {
            int a = 0;
            if (t < NBMAX && t >= off) a = s[t - off];
            __syncthreads();
            if (t < NBMAX) s[t] += a;
            __syncthreads();
        }
        if (t < nb) g_bsums[t] = s[t] - v;
    } else {
        int idx = (blockIdx.x - 1) * 256 + threadIdx.x;
        if (idx < NTYPES * DIM) {
            int t = idx / DIM, o = idx % DIM;
            float acc = 0.f;
            #pragma unroll 8
            for (int d = 0; d < DIM; d++) acc = fmaf(emb[t * DIM + d], W1[d * DIM + o], acc);
            g_htab[idx] = acc;
        }
    }
}

__global__ void k_scan3(int n, int E) {
    int i = blockIdx.x * blockDim.x + threadIdx.x;
    if (i < n) g_rowptr[i] += g_bsums[i >> 10];
    if (i == 0) g_rowptr[n] = E;
}

// CSR placement + layer-1 coefficient accumulation
__global__ void k_scatter(const int* __restrict__ ei, const int* __restrict__ node_ids, int E) {
    int e = blockIdx.x * blockDim.x + threadIdx.x;
    if (e >= E) return;
    int s = ei[e];
    int d = ei[E + e];
    int p = atomicAdd(&g_cur[d], 1);
    g_srcA[g_rowptr[d] + p] = s;
    atomicAdd(&g_c[(size_t)d * NTYPES + node_ids[s]], g_dinv[s]);
}

// Layer 1 via 17-type decomposition; writes y1s = dinv*relu(.) as fp16
__global__ void __launch_bounds__(256) k_layer1(const int* __restrict__ node_ids,
                                                const float* __restrict__ b1, int n) {
    __shared__ float4 sh[NTYPES * 32];
    __shared__ float4 sb[32];
    for (int i = threadIdx.x; i < NTYPES * 32; i += blockDim.x)
        sh[i] = ((const float4*)g_htab)[i];
    if (threadIdx.x < 32) sb[threadIdx.x] = ((const float4*)b1)[threadIdx.x];
    __syncthreads();

    int warp = threadIdx.x >> 5, lane = threadIdx.x & 31;
    int i = blockIdx.x * 8 + warp;
    if (i >= n) return;

    float di = g_dinv[i];
    int ti = node_ids[i];
    float cv = (lane < NTYPES) ? g_c[(size_t)i * NTYPES + lane] : 0.f;

    float4 acc = {0.f, 0.f, 0.f, 0.f};
    #pragma unroll
    for (int t = 0; t < NTYPES; t++) {
        float ct = __shfl_sync(0xffffffffu, cv, t);
        if (t == ti) ct += di;                 // self-loop contribution
        float4 h = sh[t * 32 + lane];
        acc.x = fmaf(ct, h.x, acc.x);
        acc.y = fmaf(ct, h.y, acc.y);
        acc.z = fmaf(ct, h.z, acc.z);
        acc.w = fmaf(ct, h.w, acc.w);
    }
    float4 bb = sb[lane];
    float4 r;
    r.x = di * fmaxf(fmaf(di, acc.x, bb.x), 0.f);
    r.y = di * fmaxf(fmaf(di, acc.y, bb.y), 0.f);
    r.z = di * fmaxf(fmaf(di, acc.z, bb.z), 0.f);
    r.w = di * fmaxf(fmaf(di, acc.w, bb.w), 0.f);
    __half2 p0 = __floats2half2_rn(r.x, r.y);
    __half2 p1 = __floats2half2_rn(r.z, r.w);
    uint2 u;
    u.x = *(unsigned int*)&p0;
    u.y = *(unsigned int*)&p1;
    ((uint2*)g_y1h)[(size_t)i * 32 + lane] = u;
}

__device__ __forceinline__ void acc_row(float4& acc, uint2 u) {
    __half2 h0 = *(__half2*)&u.x;
    __half2 h1 = *(__half2*)&u.y;
    float2 f0 = __half22float2(h0);
    float2 f1 = __half22float2(h1);
    acc.x += f0.x; acc.y += f0.y; acc.z += f1.x; acc.w += f1.y;
}

// Layer 2 aggregation (pure gather-sum of y1s) fused with graph pooling
__global__ void __launch_bounds__(256) k_layer2pool(const int* __restrict__ batch, int n) {
    __shared__ float sy[8 * DIM];
    __shared__ int sg[8];

    int warp = threadIdx.x >> 5, lane = threadIdx.x & 31;
    int i = blockIdx.x * 8 + warp;

    if (i < n) {
        const uint2* y = (const uint2*)g_y1h;
        float di = g_dinv[i];
        float4 acc = {0.f, 0.f, 0.f, 0.f};
        acc_row(acc, __ldg(&y[(size_t)i * 32 + lane]));   // self loop

        int e = g_rowptr[i], e1 = g_rowptr[i + 1];
        for (; e + 4 <= e1; e += 4) {
            int s0 = g_srcA[e], s1 = g_srcA[e + 1], s2 = g_srcA[e + 2], s3 = g_srcA[e + 3];
            uint2 u0 = __ldg(&y[(size_t)s0 * 32 + lane]);
            uint2 u1 = __ldg(&y[(size_t)s1 * 32 + lane]);
            uint2 u2 = __ldg(&y[(size_t)s2 * 32 + lane]);
            uint2 u3 = __ldg(&y[(size_t)s3 * 32 + lane]);
            acc_row(acc, u0); acc_row(acc, u1); acc_row(acc, u2); acc_row(acc, u3);
        }
        for (; e < e1; e++) {
            uint2 u0 = __ldg(&y[(size_t)g_srcA[e] * 32 + lane]);
            acc_row(acc, u0);
        }
        acc.x *= di; acc.y *= di; acc.z *= di; acc.w *= di;
        ((float4*)sy)[warp * 32 + lane] = acc;
        if (lane == 0) sg[warp] = batch[i];
    } else {
        if (lane == 0) sg[warp] = -1;
    }
    __syncthreads();

    // segmented per-block reduction into the per-graph pool
    int f = threadIdx.x;
    if (f < DIM) {
        float run = 0.f; int cg = -1; int cnt = 0;
        #pragma unroll
        for (int r = 0; r < 8; r++) {
            int g = sg[r];
            if (g < 0) continue;
            if (g != cg) {
                if (cg >= 0) {
                    atomicAdd(&g_pool[cg * DIM + f], run);
                    if (f == 0) atomicAdd(&g_gcnt[cg], cnt);
                }
                cg = g; run = 0.f; cnt = 0;
            }
            run += sy[r * DIM + f];
            cnt++;
        }
        if (cg >= 0) {
            atomicAdd(&g_pool[cg * DIM + f], run);
            if (f == 0) atomicAdd(&g_gcnt[cg], cnt);
        }
    }
}

// out[g] = (pool[g]/cnt[g]) @ W2 + b2
__global__ void k_final(const float* __restrict__ W2, const float* __restrict__ b2,
                        float* __restrict__ out) {
    int g = blockIdx.x, o = threadIdx.x;
    __shared__ float p[DIM];
    int c = g_gcnt[g];
    float inv = (c > 0) ? (1.0f / (float)c) : 0.f;
    p[o] = g_pool[g * DIM + o] * inv;
    __syncthreads();
    float acc = 0.f;
    #pragma unroll 8
    for (int d = 0; d < DIM; d++) acc = fmaf(p[d], W2[d * DIM + o], acc);
    out[g * DIM + o] = (c > 0) ? (acc + b2[o]) : 0.f;
}

// ---------------- launcher ----------------
extern "C" void kernel_launch(void* const* d_in, const int* in_sizes, int n_in,
                              void* d_out, int out_size) {
    const int* node_ids = (const int*)d_in[0];
    const int* ei       = (const int*)d_in[1];
    const int* batch    = (const int*)d_in[2];
    int base = (n_in >= 9 && in_sizes[3] == 1) ? 4 : 3;
    const float* emb = (const float*)d_in[base + 0];
    const float* W1  = (const float*)d_in[base + 1];
    const float* b1  = (const float*)d_in[base + 2];
    const float* W2  = (const float*)d_in[base + 3];
    const float* b2  = (const float*)d_in[base + 4];

    int N = in_sizes[0];
    int E = in_sizes[1] / 2;
    int G = out_size / DIM;
    int NB = (N + 1023) / 1024;

    int initN = N * NTYPES;
    if (initN < G * DIM) initN = G * DIM;

    k_init<<<(initN + 255) / 256, 256>>>(N, G);
    k_hist<<<(E + 255) / 256, 256>>>(ei, E);
    k_scan1<<<NB, 1024>>>(N);
    k_misc<<<1 + (NTYPES * DIM + 255) / 256, 256>>>(NB, emb, W1);
    k_scan3<<<(N + 255) / 256, 256>>>(N, E);
    k_scatter<<<(E + 255) / 256, 256>>>(ei, node_ids, E);
    k_layer1<<<(N + 7) / 8, 256>>>(node_ids, b1, N);
    k_layer2pool<<<(N + 7) / 8, 256>>>(batch, N);
    k_final<<<G, DIM>>>(W2, b2, (float*)d_out);
}

// round 3
// speedup vs baseline: 2.1595x; 1.0977x over previous
#include <cuda_runtime.h>
#include <cuda_fp16.h>
#include <math.h>

#define NMAX    100000
#define EMAX    1600000
#define NTYPES  17
#define DIM     128
#define GMAX    64
#define NBMAX   128

// ---------------- static scratch ----------------
__device__ int      g_cnt[NMAX];
__device__ int      g_cur[NMAX];
__device__ int      g_rowptr[NMAX];        // local-exclusive; add g_bsums[i>>10] on use
__device__ int      g_bsums[NBMAX];
__device__ int      g_srcA[EMAX];
__device__ float    g_dinv[NMAX];
__device__ int2     g_nd[NMAX];            // {dinv (as int bits), node_type}
__device__ float    g_c[(size_t)NMAX * NTYPES];
__device__ float    g_htab[NTYPES * DIM];
__device__ unsigned g_y1u[(size_t)NMAX * 32];  // fp8 e4m3: 128 feats = 32 uints per node
__device__ float    g_pool[GMAX * DIM];
__device__ int      g_gcnt[GMAX];

// ---------------- fp8 helpers ----------------
__device__ __forceinline__ unsigned pack_f4_e4m3(float4 r) {
    unsigned short p01, p23;
    asm("cvt.rn.satfinite.e4m3x2.f32 %0, %1, %2;" : "=h"(p01) : "f"(r.y), "f"(r.x));
    asm("cvt.rn.satfinite.e4m3x2.f32 %0, %1, %2;" : "=h"(p23) : "f"(r.w), "f"(r.z));
    return ((unsigned)p23 << 16) | (unsigned)p01;
}

__device__ __forceinline__ void h2acc(unsigned u, __half2& a0, __half2& a1) {
    unsigned short lo = (unsigned short)(u & 0xffffu);
    unsigned short hi = (unsigned short)(u >> 16);
    unsigned c0, c1;
    asm("cvt.rn.f16x2.e4m3x2 %0, %1;" : "=r"(c0) : "h"(lo));
    asm("cvt.rn.f16x2.e4m3x2 %0, %1;" : "=r"(c1) : "h"(hi));
    a0 = __hadd2(a0, *(__half2*)&c0);
    a1 = __hadd2(a1, *(__half2*)&c1);
}

__device__ __forceinline__ void flushacc(float4& acc, __half2& h0, __half2& h1) {
    float2 f0 = __half22float2(h0);
    float2 f1 = __half22float2(h1);
    acc.x += f0.x; acc.y += f0.y; acc.z += f1.x; acc.w += f1.y;
    h0 = __float2half2_rn(0.f);
    h1 = __float2half2_rn(0.f);
}

// ---------------- kernels ----------------

__global__ void k_init(int n, int g) {
    int i = blockIdx.x * blockDim.x + threadIdx.x;
    if (i < n) { g_cnt[i] = 0; g_cur[i] = 0; }
    if (i < n * NTYPES) g_c[i] = 0.f;
    if (i < g * DIM) g_pool[i] = 0.f;
    if (i < g) g_gcnt[i] = 0;
}

__global__ void k_hist(const int* __restrict__ ei, int E) {
    int e = blockIdx.x * blockDim.x + threadIdx.x;
    if (e < E) atomicAdd(&g_cnt[ei[E + e]], 1);
}

// per-block scan of counts; also dinv = rsqrt(deg+1) and packed (dinv,type)
__global__ void k_scan1(const int* __restrict__ node_ids, int n) {
    __shared__ int s[1024];
    int t = threadIdx.x;
    int i = blockIdx.x * 1024 + t;
    int v = (i < n) ? g_cnt[i] : 0;
    if (i < n) {
        float dv = rsqrtf((float)(v + 1));
        g_dinv[i] = dv;
        g_nd[i] = make_int2(__float_as_int(dv), node_ids[i]);
    }
    s[t] = v;
    __syncthreads();
    #pragma unroll
    for (int off = 1; off < 1024; off <<= 1) {
        int a = (t >= off) ? s[t - off] : 0;
        __syncthreads();
        s[t] += a;
        __syncthreads();
    }
    if (i < n) g_rowptr[i] = s[t] - v;
    if (t == 1023) g_bsums[blockIdx.x] = s[1023];
}

// block 0: scan of block sums;  blocks 1..: h_table = emb @ W1 (4-way MLP)
__global__ void k_misc(int nb, const float* __restrict__ emb, const float* __restrict__ W1) {
    if (blockIdx.x == 0) {
        __shared__ int s[NBMAX];
        int t = threadIdx.x;
        int v = 0;
        if (t < NBMAX) { v = (t < nb) ? g_bsums[t] : 0; s[t] = v; }
        __syncthreads();
        #pragma unroll
        for (int off = 1; off < NBMAX; off <<= 1) {
            int a = 0;
            if (t < NBMAX && t >= off) a = s[t - off];
            __syncthreads();
            if (t < NBMAX) s[t] += a;
            __syncthreads();
        }
        if (t < nb) g_bsums[t] = s[t] - v;
    } else {
        int idx = (blockIdx.x - 1) * 256 + threadIdx.x;
        if (idx < NTYPES * DIM) {
            int t = idx / DIM, o = idx % DIM;
            float a0 = 0.f, a1 = 0.f, a2 = 0.f, a3 = 0.f;
            #pragma unroll
            for (int d = 0; d < DIM; d += 4) {
                a0 = fmaf(emb[t * DIM + d + 0], W1[(d + 0) * DIM + o], a0);
                a1 = fmaf(emb[t * DIM + d + 1], W1[(d + 1) * DIM + o], a1);
                a2 = fmaf(emb[t * DIM + d + 2], W1[(d + 2) * DIM + o], a2);
                a3 = fmaf(emb[t * DIM + d + 3], W1[(d + 3) * DIM + o], a3);
            }
            g_htab[idx] = (a0 + a1) + (a2 + a3);
        }
    }
}

// CSR placement + layer-1 type-coefficient accumulation
__global__ void k_scatter(const int* __restrict__ ei, int E) {
    int e = blockIdx.x * blockDim.x + threadIdx.x;
    if (e >= E) return;
    int s = ei[e];
    int d = ei[E + e];
    int p = atomicAdd(&g_cur[d], 1);
    g_srcA[g_rowptr[d] + g_bsums[d >> 10] + p] = s;
    int2 nd = __ldg(&g_nd[s]);
    atomicAdd(&g_c[(size_t)d * NTYPES + nd.y], __int_as_float(nd.x));
}

// Layer 1 via 17-type decomposition; writes y1s = dinv*relu(.) as fp8 e4m3
__global__ void __launch_bounds__(256) k_layer1(const float* __restrict__ b1, int n) {
    __shared__ float4 sh[NTYPES * 32];
    __shared__ float4 sb[32];
    for (int i = threadIdx.x; i < NTYPES * 32; i += blockDim.x)
        sh[i] = ((const float4*)g_htab)[i];
    if (threadIdx.x < 32) sb[threadIdx.x] = ((const float4*)b1)[threadIdx.x];
    __syncthreads();

    int warp = threadIdx.x >> 5, lane = threadIdx.x & 31;
    int i = blockIdx.x * 8 + warp;
    if (i >= n) return;

    int2 nd = g_nd[i];
    float di = __int_as_float(nd.x);
    int ti = nd.y;
    float cv = (lane < NTYPES) ? g_c[(size_t)i * NTYPES + lane] : 0.f;

    float4 acc = {0.f, 0.f, 0.f, 0.f};
    #pragma unroll
    for (int t = 0; t < NTYPES; t++) {
        float ct = __shfl_sync(0xffffffffu, cv, t);
        if (t == ti) ct += di;                 // self-loop
        float4 h = sh[t * 32 + lane];
        acc.x = fmaf(ct, h.x, acc.x);
        acc.y = fmaf(ct, h.y, acc.y);
        acc.z = fmaf(ct, h.z, acc.z);
        acc.w = fmaf(ct, h.w, acc.w);
    }
    float4 bb = sb[lane];
    float4 r;
    r.x = di * fmaxf(fmaf(di, acc.x, bb.x), 0.f);
    r.y = di * fmaxf(fmaf(di, acc.y, bb.y), 0.f);
    r.z = di * fmaxf(fmaf(di, acc.z, bb.z), 0.f);
    r.w = di * fmaxf(fmaf(di, acc.w, bb.w), 0.f);
    g_y1u[(size_t)i * 32 + lane] = pack_f4_e4m3(r);
}

// Layer 2 aggregation (fp8 gather-sum) fused with graph pooling
__global__ void __launch_bounds__(256) k_layer2pool(const int* __restrict__ batch, int n, int E) {
    __shared__ float sy[8 * DIM];
    __shared__ int sg[8];

    int warp = threadIdx.x >> 5, lane = threadIdx.x & 31;
    int i = blockIdx.x * 8 + warp;

    if (i < n) {
        const unsigned* y = (const unsigned*)g_y1u;
        float di = g_dinv[i];
        float4 acc = {0.f, 0.f, 0.f, 0.f};
        __half2 h0 = __float2half2_rn(0.f), h1 = __float2half2_rn(0.f);

        h2acc(__ldg(&y[(size_t)i * 32 + lane]), h0, h1);   // self loop

        int e  = g_rowptr[i] + g_bsums[i >> 10];
        int e1 = (i + 1 < n) ? (g_rowptr[i + 1] + g_bsums[(i + 1) >> 10]) : E;

        for (; e + 8 <= e1; e += 8) {
            unsigned u0 = __ldg(&y[(size_t)g_srcA[e + 0] * 32 + lane]);
            unsigned u1 = __ldg(&y[(size_t)g_srcA[e + 1] * 32 + lane]);
            unsigned u2 = __ldg(&y[(size_t)g_srcA[e + 2] * 32 + lane]);
            unsigned u3 = __ldg(&y[(size_t)g_srcA[e + 3] * 32 + lane]);
            unsigned u4 = __ldg(&y[(size_t)g_srcA[e + 4] * 32 + lane]);
            unsigned u5 = __ldg(&y[(size_t)g_srcA[e + 5] * 32 + lane]);
            unsigned u6 = __ldg(&y[(size_t)g_srcA[e + 6] * 32 + lane]);
            unsigned u7 = __ldg(&y[(size_t)g_srcA[e + 7] * 32 + lane]);
            h2acc(u0, h0, h1); h2acc(u1, h0, h1); h2acc(u2, h0, h1); h2acc(u3, h0, h1);
            h2acc(u4, h0, h1); h2acc(u5, h0, h1); h2acc(u6, h0, h1); h2acc(u7, h0, h1);
            flushacc(acc, h0, h1);
        }
        for (; e < e1; e++)
            h2acc(__ldg(&y[(size_t)g_srcA[e] * 32 + lane]), h0, h1);
        flushacc(acc, h0, h1);

        acc.x *= di; acc.y *= di; acc.z *= di; acc.w *= di;
        ((float4*)sy)[warp * 32 + lane] = acc;
        if (lane == 0) sg[warp] = batch[i];
    } else {
        if (lane == 0) sg[warp] = -1;
    }
    __syncthreads();

    int f = threadIdx.x;
    if (f < DIM) {
        float run = 0.f; int cg = -1; int cnt = 0;
        #pragma unroll
        for (int r = 0; r < 8; r++) {
            int g = sg[r];
            if (g < 0) continue;
            if (g != cg) {
                if (cg >= 0) {
                    atomicAdd(&g_pool[cg * DIM + f], run);
                    if (f == 0) atomicAdd(&g_gcnt[cg], cnt);
                }
                cg = g; run = 0.f; cnt = 0;
            }
            run += sy[r * DIM + f];
            cnt++;
        }
        if (cg >= 0) {
            atomicAdd(&g_pool[cg * DIM + f], run);
            if (f == 0) atomicAdd(&g_gcnt[cg], cnt);
        }
    }
}

// out[g] = (pool[g]/cnt[g]) @ W2 + b2
__global__ void k_final(const float* __restrict__ W2, const float* __restrict__ b2,
                        float* __restrict__ out) {
    int g = blockIdx.x, o = threadIdx.x;
    __shared__ float p[DIM];
    int c = g_gcnt[g];
    float inv = (c > 0) ? (1.0f / (float)c) : 0.f;
    p[o] = g_pool[g * DIM + o] * inv;
    __syncthreads();
    float a0 = 0.f, a1 = 0.f, a2 = 0.f, a3 = 0.f;
    #pragma unroll
    for (int d = 0; d < DIM; d += 4) {
        a0 = fmaf(p[d + 0], W2[(d + 0) * DIM + o], a0);
        a1 = fmaf(p[d + 1], W2[(d + 1) * DIM + o], a1);
        a2 = fmaf(p[d + 2], W2[(d + 2) * DIM + o], a2);
        a3 = fmaf(p[d + 3], W2[(d + 3) * DIM + o], a3);
    }
    out[g * DIM + o] = (c > 0) ? ((a0 + a1) + (a2 + a3) + b2[o]) : 0.f;
}

// ---------------- launcher ----------------
extern "C" void kernel_launch(void* const* d_in, const int* in_sizes, int n_in,
                              void* d_out, int out_size) {
    const int* node_ids = (const int*)d_in[0];
    const int* ei       = (const int*)d_in[1];
    const int* batch    = (const int*)d_in[2];
    int base = (n_in >= 9 && in_sizes[3] == 1) ? 4 : 3;
    const float* emb = (const float*)d_in[base + 0];
    const float* W1  = (const float*)d_in[base + 1];
    const float* b1  = (const float*)d_in[base + 2];
    const float* W2  = (const float*)d_in[base + 3];
    const float* b2  = (const float*)d_in[base + 4];

    int N = in_sizes[0];
    int E = in_sizes[1] / 2;
    int G = out_size / DIM;
    int NB = (N + 1023) / 1024;

    int initN = N * NTYPES;
    if (initN < G * DIM) initN = G * DIM;

    k_init<<<(initN + 255) / 256, 256>>>(N, G);
    k_hist<<<(E + 255) / 256, 256>>>(ei, E);
    k_scan1<<<NB, 1024>>>(node_ids, N);
    k_misc<<<1 + (NTYPES * DIM + 255) / 256, 256>>>(NB, emb, W1);
    k_scatter<<<(E + 255) / 256, 256>>>(ei, E);
    k_layer1<<<(N + 7) / 8, 256>>>(b1, N);
    k_layer2pool<<<(N + 7) / 8, 256>>>(batch, N, E);
    k_final<<<G, DIM>>>(W2, b2, (float*)d_out);
}